// round 1
// baseline (speedup 1.0000x reference)
#include <cuda_runtime.h>
#include <math.h>

#define Bz   4
#define Sq   4096
#define Hn   8
#define Dn   64
#define LNE  512          // H*D
#define TS   8            // tokens per GEMM tile == cumsum tile
#define NT   512          // Sq/TS
#define GN   16           // cumsum groups
#define GT   32           // tiles per group (GN*GT == NT)
#define CG   32           // lgate scan chunk
#define NCH  128          // Sq/CG
#define ASTR 68           // shared A stride (pad to dodge bank conflicts, mult of 4)

// ---- scratch (allocation-free: __device__ globals) ----
__device__ float g_h3  [(size_t)Bz*Sq*Hn*192];   // 100.7MB
__device__ float g_fg  [(size_t)Bz*Sq*LNE];
__device__ float g_igh [(size_t)Bz*Sq*LNE];
__device__ float g_cell[(size_t)Bz*Sq*LNE];
__device__ float g_tsum[(size_t)Bz*NT*LNE];
__device__ float g_toff[(size_t)Bz*NT*LNE];
__device__ float g_gsum[(size_t)Bz*GN*LNE];
__device__ float g_goff[(size_t)Bz*GN*LNE];
__device__ float g_cA  [(size_t)Bz*NCH*LNE];
__device__ float g_cB  [(size_t)Bz*NCH*LNE];
__device__ float g_cIn [(size_t)Bz*NCH*LNE];

__device__ __forceinline__ float sigm(float x){ return 1.f/(1.f+expf(-x)); }

// ---- packed f32x2 helpers (PTX-only on Blackwell) ----
__device__ __forceinline__ unsigned long long pk2(float x, float y){
    unsigned long long r;
    asm("mov.b64 %0, {%1,%2};" : "=l"(r) : "f"(x), "f"(y));
    return r;
}
__device__ __forceinline__ void fma2(unsigned long long &d, unsigned long long a, unsigned long long b){
    asm("fma.rn.f32x2 %0, %1, %2, %3;" : "=l"(d) : "l"(a), "l"(b), "l"(d));
}
__device__ __forceinline__ float2 up2(unsigned long long v){
    float2 f;
    asm("mov.b64 {%0,%1}, %2;" : "=f"(f.x), "=f"(f.y) : "l"(v));
    return f;
}

// ============ cumsum chunked scan ============
// K1: per-tile (8-token) sums per lane
__global__ void k_tilesum(const float* __restrict__ x){
    int blk = blockIdx.x;            // b*NT + t
    int b = blk >> 9, t = blk & 511;
    int lane = threadIdx.x;
    const float* p = x + ((size_t)(b*Sq + t*TS))*LNE + lane;
    float s = 0.f;
    #pragma unroll
    for(int i=0;i<TS;i++) s += p[(size_t)i*LNE];
    g_tsum[(size_t)blk*LNE + lane] = s;
}

// K2: per-group sums (32 tiles each) — all loads independent
__global__ void k_gsum(){
    int blk = blockIdx.x;            // b*GN + g
    int b = blk >> 4, g = blk & 15;
    int lane = threadIdx.x;
    size_t base = ((size_t)b*NT + g*GT)*LNE + lane;
    float s = 0.f;
    #pragma unroll
    for(int i=0;i<GT;i++) s += g_tsum[base + (size_t)i*LNE];
    g_gsum[(size_t)blk*LNE + lane] = s;
}

// K3: exclusive scan over the 16 groups
__global__ void k_gscan(){
    int b = blockIdx.x, lane = threadIdx.x;
    size_t base = ((size_t)b*GN)*LNE + lane;
    float v[GN];
    #pragma unroll
    for(int i=0;i<GN;i++) v[i] = g_gsum[base + (size_t)i*LNE];
    float run = 0.f;
    #pragma unroll
    for(int i=0;i<GN;i++){ g_goff[base + (size_t)i*LNE] = run; run += v[i]; }
}

// K4: exclusive scan over tiles within group (+group offset) -> g_toff
__global__ void k_tscan(){
    int blk = blockIdx.x;            // b*GN + g
    int b = blk >> 4, g = blk & 15;
    int lane = threadIdx.x;
    float run = g_goff[(size_t)blk*LNE + lane];
    size_t base = ((size_t)b*NT + g*GT)*LNE + lane;
    float v[GT];
    #pragma unroll
    for(int i=0;i<GT;i++) v[i] = g_tsum[base + (size_t)i*LNE];
    #pragma unroll
    for(int i=0;i<GT;i++){ g_toff[base + (size_t)i*LNE] = run; run += v[i]; }
}

// ============ LN + GEMM1 (hid) ============
// block = (b, 8-token tile); A = [64 rows (s*8+h)] x [128 cols: x | LN(csum)]
// C[64x192] = A @ W_hid, +bias, -> g_h3
__global__ __launch_bounds__(256) void k_ln_gemm1(
    const float* __restrict__ x,  const float* __restrict__ Wh,
    const float* __restrict__ bh, const float* __restrict__ gamma,
    const float* __restrict__ beta)
{
    __shared__ __align__(16) float At[128*ASTR];   // transposed: At[k][r]
    __shared__ float s_mean[TS], s_rstd[TS];
    int blk = blockIdx.x;
    int b = blk >> 9, t = blk & 511;
    int tid = threadIdx.x;
    int s0 = t*TS;

    // load x tile (contiguous 4096 floats) -> At[k][r], k<64
    const float4* xin = reinterpret_cast<const float4*>(x + ((size_t)(b*Sq + s0))*LNE);
    #pragma unroll
    for(int q=0;q<4;q++){
        int i = tid + q*256;
        float4 v = xin[i];
        int lin = i*4;
        int s = lin >> 9, lam = lin & 511, h = lam >> 6, k = lam & 63;
        int r = s*8 + h;
        At[(k  )*ASTR + r] = v.x; At[(k+1)*ASTR + r] = v.y;
        At[(k+2)*ASTR + r] = v.z; At[(k+3)*ASTR + r] = v.w;
    }
    __syncthreads();

    // exclusive local cumsum + tile offset -> raw csum into At[64+k][r]
    #pragma unroll
    for(int q=0;q<2;q++){
        int lam = tid + q*256;
        int h = lam >> 6, k = lam & 63;
        float run = g_toff[((size_t)(b*NT + t))*LNE + lam];
        #pragma unroll
        for(int s=0;s<TS;s++){
            int r = s*8 + h;
            float xv = At[k*ASTR + r];
            At[(64+k)*ASTR + r] = run;
            run += xv;
        }
    }
    __syncthreads();

    // LN stats over (H,D)=512 per s: warp w handles s=w
    {
        int w = tid >> 5, lanei = tid & 31;
        float sum = 0.f, sq = 0.f;
        for(int idx=lanei; idx<512; idx+=32){
            int h = idx >> 6, k = idx & 63;
            float v = At[(64+k)*ASTR + w*8 + h];
            sum += v; sq += v*v;
        }
        #pragma unroll
        for(int o=16;o>0;o>>=1){
            sum += __shfl_xor_sync(0xffffffffu, sum, o);
            sq  += __shfl_xor_sync(0xffffffffu, sq,  o);
        }
        if(lanei==0){
            float m = sum * (1.f/512.f);
            float var = sq * (1.f/512.f) - m*m;
            s_mean[w] = m;
            s_rstd[w] = rsqrtf(var + 1e-5f);
        }
    }
    __syncthreads();

    // normalize in place (+gamma/beta)
    #pragma unroll
    for(int q=0;q<16;q++){
        int idx = tid + q*256;
        int s = idx >> 9, lam = idx & 511, h = lam >> 6, k = lam & 63;
        int p = (64+k)*ASTR + s*8 + h;
        float v = At[p];
        At[p] = (v - s_mean[s]) * s_rstd[s] * gamma[lam] + beta[lam];
    }
    __syncthreads();

    // GEMM: C[64x192] = A[64x128] @ W[128x192], f32x2 packed
    int tx = tid & 15, ty = tid >> 4;
    int r0 = ty*4, c0 = tx*12;
    unsigned long long acc[4][6];
    #pragma unroll
    for(int i=0;i<4;i++)
        #pragma unroll
        for(int j=0;j<6;j++) acc[i][j] = 0ull;

    #pragma unroll 2
    for(int k=0;k<128;k++){
        float4 a4 = *reinterpret_cast<const float4*>(&At[k*ASTR + r0]);
        unsigned long long aa[4];
        aa[0]=pk2(a4.x,a4.x); aa[1]=pk2(a4.y,a4.y); aa[2]=pk2(a4.z,a4.z); aa[3]=pk2(a4.w,a4.w);
        const unsigned long long* wr =
            reinterpret_cast<const unsigned long long*>(Wh + k*192 + c0);
        unsigned long long wv[6];
        #pragma unroll
        for(int j=0;j<6;j++) wv[j] = wr[j];
        #pragma unroll
        for(int i=0;i<4;i++)
            #pragma unroll
            for(int j=0;j<6;j++) fma2(acc[i][j], aa[i], wv[j]);
    }

    // epilogue: +bias, write h3
    #pragma unroll
    for(int i=0;i<4;i++){
        int r = r0 + i, s = r >> 3, h = r & 7;
        float* dst = g_h3 + (((size_t)(b*Sq + s0 + s)*Hn + h)*192) + c0;
        #pragma unroll
        for(int j=0;j<6;j++){
            float2 v = up2(acc[i][j]);
            v.x += bh[c0 + 2*j];
            v.y += bh[c0 + 2*j + 1];
            *reinterpret_cast<float2*>(dst + 2*j) = v;
        }
    }
}

// ============ gates + per-chunk lgate partials ============
__global__ void k_gates(){
    int blk = blockIdx.x;            // b*NCH + ch
    int b = blk >> 7, ch = blk & 127;
    int lam = threadIdx.x;
    int h = lam >> 6, k = lam & 63;
    const float* base = g_h3 + (((size_t)(b*Sq + ch*CG)*Hn + h)*192) + k;
    size_t oidx = ((size_t)(b*Sq + ch*CG))*LNE + lam;
    float A = 1.f, Bv = 0.f;
    #pragma unroll 4
    for(int s=0;s<CG;s++){
        float ig = base[0], fgt = base[64], hd = base[128];
        float fg  = sigm(fgt);
        float igh = sigm(ig) * fmaxf(hd, 0.f);
        g_fg[oidx]  = fg;
        g_igh[oidx] = igh;
        A *= fg;
        Bv = Bv*fg + igh;
        base += Hn*192;
        oidx += LNE;
    }
    g_cA[((size_t)(b*NCH + ch))*LNE + lam] = A;
    g_cB[((size_t)(b*NCH + ch))*LNE + lam] = Bv;
}

// scan across the 128 chunks (FMA chain only; loads independent)
__global__ void k_cellscan(const float* __restrict__ icx){
    int b = blockIdx.x, lam = threadIdx.x;
    float c = icx[lam];
    size_t base = (size_t)b*NCH*LNE + lam;
    #pragma unroll 8
    for(int t=0;t<NCH;t++){
        float a = g_cA[base + (size_t)t*LNE];
        float v = g_cB[base + (size_t)t*LNE];
        g_cIn[base + (size_t)t*LNE] = c;
        c = a*c + v;
    }
}

// expand within chunk -> g_cell
__global__ void k_cellwrite(){
    int blk = blockIdx.x;
    int b = blk >> 7, ch = blk & 127;
    int lam = threadIdx.x;
    float c = g_cIn[((size_t)(b*NCH + ch))*LNE + lam];
    size_t idx = ((size_t)(b*Sq + ch*CG))*LNE + lam;
    #pragma unroll 4
    for(int s=0;s<CG;s++){
        c = g_fg[idx]*c + g_igh[idx];
        g_cell[idx] = c;
        idx += LNE;
    }
}

// ============ GEMM2 (og) + output ============
__global__ __launch_bounds__(256) void k_gemm2(
    const float* __restrict__ x, const float* __restrict__ Wo,
    const float* __restrict__ bo, float* __restrict__ out)
{
    __shared__ __align__(16) float At[128*ASTR];
    int blk = blockIdx.x;
    int b = blk >> 9, t = blk & 511;
    int tid = threadIdx.x;
    int s0 = t*TS;

    const float4* xin = reinterpret_cast<const float4*>(x      + ((size_t)(b*Sq + s0))*LNE);
    const float4* cin = reinterpret_cast<const float4*>(g_cell + ((size_t)(b*Sq + s0))*LNE);
    #pragma unroll
    for(int q=0;q<4;q++){
        int i = tid + q*256;
        float4 v  = xin[i];
        float4 cv = cin[i];
        int lin = i*4;
        int s = lin >> 9, lam = lin & 511, h = lam >> 6, k = lam & 63;
        int r = s*8 + h;
        At[(k   )*ASTR + r] = v.x;  At[(k+1 )*ASTR + r] = v.y;
        At[(k+2 )*ASTR + r] = v.z;  At[(k+3 )*ASTR + r] = v.w;
        At[(64+k)*ASTR + r] = cv.x; At[(65+k)*ASTR + r] = cv.y;
        At[(66+k)*ASTR + r] = cv.z; At[(67+k)*ASTR + r] = cv.w;
    }
    __syncthreads();

    int tx = tid & 15, ty = tid >> 4;
    int r0 = ty*4, c0 = tx*4;
    unsigned long long acc[4][2];
    #pragma unroll
    for(int i=0;i<4;i++){ acc[i][0]=0ull; acc[i][1]=0ull; }

    #pragma unroll 2
    for(int k=0;k<128;k++){
        float4 a4 = *reinterpret_cast<const float4*>(&At[k*ASTR + r0]);
        unsigned long long aa[4];
        aa[0]=pk2(a4.x,a4.x); aa[1]=pk2(a4.y,a4.y); aa[2]=pk2(a4.z,a4.z); aa[3]=pk2(a4.w,a4.w);
        const unsigned long long* wr =
            reinterpret_cast<const unsigned long long*>(Wo + k*64 + c0);
        unsigned long long w0 = wr[0], w1 = wr[1];
        #pragma unroll
        for(int i=0;i<4;i++){ fma2(acc[i][0], aa[i], w0); fma2(acc[i][1], aa[i], w1); }
    }

    #pragma unroll
    for(int i=0;i<4;i++){
        int r = r0 + i, s = r >> 3, h = r & 7;
        float2 v0 = up2(acc[i][0]), v1 = up2(acc[i][1]);
        float o0 = sigm(v0.x + bo[c0  ]);
        float o1 = sigm(v0.y + bo[c0+1]);
        float o2 = sigm(v1.x + bo[c0+2]);
        float o3 = sigm(v1.y + bo[c0+3]);
        float c0v = At[(64+c0  )*ASTR + r];
        float c1v = At[(64+c0+1)*ASTR + r];
        float c2v = At[(64+c0+2)*ASTR + r];
        float c3v = At[(64+c0+3)*ASTR + r];
        float4 res = make_float4(o0*c0v, o1*c1v, o2*c2v, o3*c3v);
        *reinterpret_cast<float4*>(out + (((size_t)(b*Sq + s0 + s)*Hn + h)*64) + c0) = res;
    }
}

extern "C" void kernel_launch(void* const* d_in, const int* in_sizes, int n_in,
                              void* d_out, int out_size)
{
    const float* x     = (const float*)d_in[0];
    const float* Wh    = (const float*)d_in[1];
    const float* bh    = (const float*)d_in[2];
    const float* Wo    = (const float*)d_in[3];
    const float* bo    = (const float*)d_in[4];
    const float* gamma = (const float*)d_in[5];
    const float* beta  = (const float*)d_in[6];
    const float* icx   = (const float*)d_in[7];
    float* out = (float*)d_out;

    k_tilesum  <<<Bz*NT , 512>>>(x);
    k_gsum     <<<Bz*GN , 512>>>();
    k_gscan    <<<Bz    , 512>>>();
    k_tscan    <<<Bz*GN , 512>>>();
    k_ln_gemm1 <<<Bz*NT , 256>>>(x, Wh, bh, gamma, beta);
    k_gates    <<<Bz*NCH, 512>>>();
    k_cellscan <<<Bz    , 512>>>(icx);
    k_cellwrite<<<Bz*NCH, 512>>>();
    k_gemm2    <<<Bz*NT , 256>>>(x, Wo, bo, out);
}

// round 2
// speedup vs baseline: 1.3444x; 1.3444x over previous
#include <cuda_runtime.h>
#include <math.h>

#define Bz   4
#define Sq   4096
#define Hn   8
#define Dn   64
#define LNE  512          // H*D
#define TS   8            // tokens per GEMM tile == scan tile
#define NT   512          // Sq/TS
#define GN   16           // scan groups
#define GT   32           // tiles per group (GN*GT == NT)
#define ASTR 68           // shared A stride (pad, mult of 4)
#define FS   68           // Fs/Is stride (64*68*2 == 128*68 exactly)

// ---- scratch (allocation-free: __device__ globals) ----
__device__ float g_fg  [(size_t)Bz*Sq*LNE];
__device__ float g_igh [(size_t)Bz*Sq*LNE];
__device__ float g_tsum[(size_t)Bz*NT*LNE];
__device__ float g_toff[(size_t)Bz*NT*LNE];
__device__ float g_gsum[(size_t)Bz*GN*LNE];
__device__ float g_goff[(size_t)Bz*GN*LNE];
__device__ float g_tA  [(size_t)Bz*NT*LNE];
__device__ float g_tB  [(size_t)Bz*NT*LNE];
__device__ float g_cIn [(size_t)Bz*NT*LNE];
__device__ float g_gA  [(size_t)Bz*GN*LNE];
__device__ float g_gB  [(size_t)Bz*GN*LNE];
__device__ float g_gcin[(size_t)Bz*GN*LNE];

__device__ __forceinline__ float sigm(float x){
    return __fdividef(1.f, 1.f + __expf(-x));
}

// ---- packed f32x2 helpers (PTX-only on Blackwell) ----
__device__ __forceinline__ unsigned long long pk2(float x, float y){
    unsigned long long r;
    asm("mov.b64 %0, {%1,%2};" : "=l"(r) : "f"(x), "f"(y));
    return r;
}
__device__ __forceinline__ void fma2(unsigned long long &d, unsigned long long a, unsigned long long b){
    asm("fma.rn.f32x2 %0, %1, %2, %3;" : "=l"(d) : "l"(a), "l"(b), "l"(d));
}
__device__ __forceinline__ float2 up2(unsigned long long v){
    float2 f;
    asm("mov.b64 {%0,%1}, %2;" : "=f"(f.x), "=f"(f.y) : "l"(v));
    return f;
}

// ============ cumsum chunked scan (exclusive, along S) ============
__global__ void k_tilesum(const float* __restrict__ x){
    int blk = blockIdx.x;            // b*NT + t
    int b = blk >> 9, t = blk & 511;
    int lane = threadIdx.x;
    const float* p = x + ((size_t)(b*Sq + t*TS))*LNE + lane;
    float s = 0.f;
    #pragma unroll
    for(int i=0;i<TS;i++) s += p[(size_t)i*LNE];
    g_tsum[(size_t)blk*LNE + lane] = s;
}

__global__ void k_gsum(){
    int blk = blockIdx.x;            // b*GN + g
    int b = blk >> 4, g = blk & 15;
    int lane = threadIdx.x;
    size_t base = ((size_t)b*NT + g*GT)*LNE + lane;
    float s = 0.f;
    #pragma unroll
    for(int i=0;i<GT;i++) s += g_tsum[base + (size_t)i*LNE];
    g_gsum[(size_t)blk*LNE + lane] = s;
}

__global__ void k_gscan(){
    int b = blockIdx.x, lane = threadIdx.x;
    size_t base = ((size_t)b*GN)*LNE + lane;
    float v[GN];
    #pragma unroll
    for(int i=0;i<GN;i++) v[i] = g_gsum[base + (size_t)i*LNE];
    float run = 0.f;
    #pragma unroll
    for(int i=0;i<GN;i++){ g_goff[base + (size_t)i*LNE] = run; run += v[i]; }
}

__global__ void k_tscan(){
    int blk = blockIdx.x;            // b*GN + g
    int b = blk >> 4, g = blk & 15;
    int lane = threadIdx.x;
    float run = g_goff[(size_t)blk*LNE + lane];
    size_t base = ((size_t)b*NT + g*GT)*LNE + lane;
    float v[GT];
    #pragma unroll
    for(int i=0;i<GT;i++) v[i] = g_tsum[base + (size_t)i*LNE];
    #pragma unroll
    for(int i=0;i<GT;i++){ g_toff[base + (size_t)i*LNE] = run; run += v[i]; }
}

// ============ LN + GEMM1 + gates + lgate tile partials ============
// block = (b, 8-token tile); A = [64 rows (s*8+h)] x [128 k: x | LN(csum)]
// thread (tx,ty): rows ty*4..+3, gate-cols j0=tx*4..+3 as triple {j, j+64, j+128}
__global__ __launch_bounds__(256) void k_ln_gemm1(
    const float* __restrict__ x,  const float* __restrict__ Wh,
    const float* __restrict__ bh, const float* __restrict__ gamma,
    const float* __restrict__ beta)
{
    __shared__ __align__(16) float sbuf[128*ASTR];   // At, later Fs|Is
    __shared__ float s_mean[TS], s_rstd[TS];
    float* At = sbuf;
    int blk = blockIdx.x;
    int b = blk >> 9, t = blk & 511;
    int tid = threadIdx.x;
    int s0 = t*TS;

    // load x tile -> At[k][r], k<64  (r = s*8+h)
    const float4* xin = reinterpret_cast<const float4*>(x + ((size_t)(b*Sq + s0))*LNE);
    #pragma unroll
    for(int q=0;q<4;q++){
        int i = tid + q*256;
        float4 v = xin[i];
        int lin = i*4;
        int s = lin >> 9, lam = lin & 511, h = lam >> 6, k = lam & 63;
        int r = s*8 + h;
        At[(k  )*ASTR + r] = v.x; At[(k+1)*ASTR + r] = v.y;
        At[(k+2)*ASTR + r] = v.z; At[(k+3)*ASTR + r] = v.w;
    }
    __syncthreads();

    // exclusive local cumsum + tile offset -> raw csum into At[64+k][r]
    #pragma unroll
    for(int q=0;q<2;q++){
        int lam = tid + q*256;
        int h = lam >> 6, k = lam & 63;
        float run = g_toff[((size_t)(b*NT + t))*LNE + lam];
        #pragma unroll
        for(int s=0;s<TS;s++){
            int r = s*8 + h;
            float xv = At[k*ASTR + r];
            At[(64+k)*ASTR + r] = run;
            run += xv;
        }
    }
    __syncthreads();

    // LN stats over 512 per s: warp w handles s=w
    {
        int w = tid >> 5, lanei = tid & 31;
        float sum = 0.f, sq = 0.f;
        for(int idx=lanei; idx<512; idx+=32){
            int h = idx >> 6, k = idx & 63;
            float v = At[(64+k)*ASTR + w*8 + h];
            sum += v; sq += v*v;
        }
        #pragma unroll
        for(int o=16;o>0;o>>=1){
            sum += __shfl_xor_sync(0xffffffffu, sum, o);
            sq  += __shfl_xor_sync(0xffffffffu, sq,  o);
        }
        if(lanei==0){
            float m = sum * (1.f/512.f);
            float var = sq * (1.f/512.f) - m*m;
            s_mean[w] = m;
            s_rstd[w] = rsqrtf(var + 1e-5f);
        }
    }
    __syncthreads();

    // normalize in place (+gamma/beta)
    #pragma unroll
    for(int q=0;q<16;q++){
        int idx = tid + q*256;
        int s = idx >> 9, lam = idx & 511, h = lam >> 6, k = lam & 63;
        int p = (64+k)*ASTR + s*8 + h;
        float v = At[p];
        At[p] = (v - s_mean[s]) * s_rstd[s] * gamma[lam] + beta[lam];
    }
    __syncthreads();

    // GEMM: each thread -> rows r0..r0+3, gate cols {j0..j0+3} x {ig,fg,hd}
    int tx = tid & 15, ty = tid >> 4;
    int r0 = ty*4, j0 = tx*4;
    unsigned long long acc[3][4][2];
    #pragma unroll
    for(int g=0;g<3;g++)
        #pragma unroll
        for(int i=0;i<4;i++){ acc[g][i][0]=0ull; acc[g][i][1]=0ull; }

    const float* w0b = Wh + j0;
    const float* w1b = Wh + 64 + j0;
    const float* w2b = Wh + 128 + j0;

    #pragma unroll 2
    for(int k=0;k<128;k++){
        float4 a4 = *reinterpret_cast<const float4*>(&At[k*ASTR + r0]);
        unsigned long long aa[4];
        aa[0]=pk2(a4.x,a4.x); aa[1]=pk2(a4.y,a4.y); aa[2]=pk2(a4.z,a4.z); aa[3]=pk2(a4.w,a4.w);
        unsigned long long wv[3][2];
        const unsigned long long* p0 = reinterpret_cast<const unsigned long long*>(w0b + k*192);
        const unsigned long long* p1 = reinterpret_cast<const unsigned long long*>(w1b + k*192);
        const unsigned long long* p2 = reinterpret_cast<const unsigned long long*>(w2b + k*192);
        wv[0][0]=p0[0]; wv[0][1]=p0[1];
        wv[1][0]=p1[0]; wv[1][1]=p1[1];
        wv[2][0]=p2[0]; wv[2][1]=p2[1];
        #pragma unroll
        for(int i=0;i<4;i++){
            fma2(acc[0][i][0], aa[i], wv[0][0]); fma2(acc[0][i][1], aa[i], wv[0][1]);
            fma2(acc[1][i][0], aa[i], wv[1][0]); fma2(acc[1][i][1], aa[i], wv[1][1]);
            fma2(acc[2][i][0], aa[i], wv[2][0]); fma2(acc[2][i][1], aa[i], wv[2][1]);
        }
    }
    __syncthreads();   // done reading At; sbuf becomes Fs|Is

    float* Fs = sbuf;            // [64][FS]
    float* Is = sbuf + 64*FS;    // [64][FS]
    float big[4], bfg[4], bhd[4];
    #pragma unroll
    for(int jj=0;jj<4;jj++){
        big[jj] = bh[j0+jj]; bfg[jj] = bh[64+j0+jj]; bhd[jj] = bh[128+j0+jj];
    }

    // gates in registers, write fg/igh to global + shared
    #pragma unroll
    for(int i=0;i<4;i++){
        int r = r0 + i, s = r >> 3, h = r & 7;
        float2 i01 = up2(acc[0][i][0]), i23 = up2(acc[0][i][1]);
        float2 f01 = up2(acc[1][i][0]), f23 = up2(acc[1][i][1]);
        float2 h01 = up2(acc[2][i][0]), h23 = up2(acc[2][i][1]);
        float ig[4] = {i01.x+big[0], i01.y+big[1], i23.x+big[2], i23.y+big[3]};
        float fr[4] = {f01.x+bfg[0], f01.y+bfg[1], f23.x+bfg[2], f23.y+bfg[3]};
        float hd[4] = {h01.x+bhd[0], h01.y+bhd[1], h23.x+bhd[2], h23.y+bhd[3]};
        float4 f4, g4;
        f4.x = sigm(fr[0]); f4.y = sigm(fr[1]); f4.z = sigm(fr[2]); f4.w = sigm(fr[3]);
        g4.x = sigm(ig[0])*fmaxf(hd[0],0.f);
        g4.y = sigm(ig[1])*fmaxf(hd[1],0.f);
        g4.z = sigm(ig[2])*fmaxf(hd[2],0.f);
        g4.w = sigm(ig[3])*fmaxf(hd[3],0.f);
        size_t gi = ((size_t)(b*Sq + s0 + s))*LNE + h*64 + j0;
        *reinterpret_cast<float4*>(&g_fg [gi]) = f4;
        *reinterpret_cast<float4*>(&g_igh[gi]) = g4;
        *reinterpret_cast<float4*>(&Fs[r*FS + j0]) = f4;
        *reinterpret_cast<float4*>(&Is[r*FS + j0]) = g4;
    }
    __syncthreads();

    // per-tile lgate partials: A = prod fg, B = fold(B*fg + igh) over s=0..7
    #pragma unroll
    for(int q=0;q<2;q++){
        int lam = tid + q*256;
        int h = lam >> 6, d = lam & 63;
        float A = 1.f, Bv = 0.f;
        #pragma unroll
        for(int s=0;s<TS;s++){
            int r = s*8 + h;
            float f = Fs[r*FS + d];
            float v = Is[r*FS + d];
            Bv = Bv*f + v;
            A *= f;
        }
        size_t ti = ((size_t)(b*NT + t))*LNE + lam;
        g_tA[ti] = A;
        g_tB[ti] = Bv;
    }
}

// ============ cell carry scan over tiles (3-level) ============
__global__ void k_cgsum(){
    int blk = blockIdx.x;            // b*GN + g
    int b = blk >> 4, g = blk & 15;
    int lane = threadIdx.x;
    size_t base = ((size_t)b*NT + g*GT)*LNE + lane;
    float A = 1.f, Bv = 0.f;
    #pragma unroll
    for(int i=0;i<GT;i++){
        float a = g_tA[base + (size_t)i*LNE];
        float v = g_tB[base + (size_t)i*LNE];
        Bv = Bv*a + v;
        A *= a;
    }
    g_gA[(size_t)blk*LNE + lane] = A;
    g_gB[(size_t)blk*LNE + lane] = Bv;
}

__global__ void k_cgscan(const float* __restrict__ icx){
    int b = blockIdx.x, lane = threadIdx.x;
    float c = icx[lane];
    size_t base = ((size_t)b*GN)*LNE + lane;
    #pragma unroll
    for(int g=0;g<GN;g++){
        g_gcin[base + (size_t)g*LNE] = c;
        c = g_gA[base + (size_t)g*LNE]*c + g_gB[base + (size_t)g*LNE];
    }
}

__global__ void k_ctscan(){
    int blk = blockIdx.x;            // b*GN + g
    int b = blk >> 4, g = blk & 15;
    int lane = threadIdx.x;
    float c = g_gcin[(size_t)blk*LNE + lane];
    size_t base = ((size_t)b*NT + g*GT)*LNE + lane;
    #pragma unroll
    for(int i=0;i<GT;i++){
        g_cIn[base + (size_t)i*LNE] = c;
        c = g_tA[base + (size_t)i*LNE]*c + g_tB[base + (size_t)i*LNE];
    }
}

// ============ GEMM2 (og) + cell recompute + output ============
__global__ __launch_bounds__(256) void k_gemm2(
    const float* __restrict__ x, const float* __restrict__ Wo,
    const float* __restrict__ bo, float* __restrict__ out)
{
    __shared__ __align__(16) float At[128*ASTR];
    int blk = blockIdx.x;
    int b = blk >> 9, t = blk & 511;
    int tid = threadIdx.x;
    int s0 = t*TS;

    const float4* xin = reinterpret_cast<const float4*>(x + ((size_t)(b*Sq + s0))*LNE);
    #pragma unroll
    for(int q=0;q<4;q++){
        int i = tid + q*256;
        float4 v = xin[i];
        int lin = i*4;
        int s = lin >> 9, lam = lin & 511, h = lam >> 6, k = lam & 63;
        int r = s*8 + h;
        At[(k  )*ASTR + r] = v.x; At[(k+1)*ASTR + r] = v.y;
        At[(k+2)*ASTR + r] = v.z; At[(k+3)*ASTR + r] = v.w;
    }

    // recompute cell from carry + fg/igh -> At[64+k][r]
    #pragma unroll
    for(int q=0;q<2;q++){
        int lam = tid + q*256;
        int h = lam >> 6, k = lam & 63;
        float c = g_cIn[((size_t)(b*NT + t))*LNE + lam];
        size_t idx = ((size_t)(b*Sq + s0))*LNE + lam;
        #pragma unroll
        for(int s=0;s<TS;s++){
            c = g_fg[idx]*c + g_igh[idx];
            At[(64+k)*ASTR + s*8 + h] = c;
            idx += LNE;
        }
    }
    __syncthreads();

    int tx = tid & 15, ty = tid >> 4;
    int r0 = ty*4, c0 = tx*4;
    unsigned long long acc[4][2];
    #pragma unroll
    for(int i=0;i<4;i++){ acc[i][0]=0ull; acc[i][1]=0ull; }

    #pragma unroll 2
    for(int k=0;k<128;k++){
        float4 a4 = *reinterpret_cast<const float4*>(&At[k*ASTR + r0]);
        unsigned long long aa[4];
        aa[0]=pk2(a4.x,a4.x); aa[1]=pk2(a4.y,a4.y); aa[2]=pk2(a4.z,a4.z); aa[3]=pk2(a4.w,a4.w);
        const unsigned long long* wr =
            reinterpret_cast<const unsigned long long*>(Wo + k*64 + c0);
        unsigned long long w0 = wr[0], w1 = wr[1];
        #pragma unroll
        for(int i=0;i<4;i++){ fma2(acc[i][0], aa[i], w0); fma2(acc[i][1], aa[i], w1); }
    }

    #pragma unroll
    for(int i=0;i<4;i++){
        int r = r0 + i, s = r >> 3, h = r & 7;
        float2 v0 = up2(acc[i][0]), v1 = up2(acc[i][1]);
        float o0 = sigm(v0.x + bo[c0  ]);
        float o1 = sigm(v0.y + bo[c0+1]);
        float o2 = sigm(v1.x + bo[c0+2]);
        float o3 = sigm(v1.y + bo[c0+3]);
        float c0v = At[(64+c0  )*ASTR + r];
        float c1v = At[(64+c0+1)*ASTR + r];
        float c2v = At[(64+c0+2)*ASTR + r];
        float c3v = At[(64+c0+3)*ASTR + r];
        float4 res = make_float4(o0*c0v, o1*c1v, o2*c2v, o3*c3v);
        *reinterpret_cast<float4*>(out + (((size_t)(b*Sq + s0 + s)*Hn + h)*64) + c0) = res;
    }
}

extern "C" void kernel_launch(void* const* d_in, const int* in_sizes, int n_in,
                              void* d_out, int out_size)
{
    const float* x     = (const float*)d_in[0];
    const float* Wh    = (const float*)d_in[1];
    const float* bh    = (const float*)d_in[2];
    const float* Wo    = (const float*)d_in[3];
    const float* bo    = (const float*)d_in[4];
    const float* gamma = (const float*)d_in[5];
    const float* beta  = (const float*)d_in[6];
    const float* icx   = (const float*)d_in[7];
    float* out = (float*)d_out;

    k_tilesum <<<Bz*NT, 512>>>(x);
    k_gsum    <<<Bz*GN, 512>>>();
    k_gscan   <<<Bz   , 512>>>();
    k_tscan   <<<Bz*GN, 512>>>();
    k_ln_gemm1<<<Bz*NT, 256>>>(x, Wh, bh, gamma, beta);
    k_cgsum   <<<Bz*GN, 512>>>();
    k_cgscan  <<<Bz   , 512>>>(icx);
    k_ctscan  <<<Bz*GN, 512>>>();
    k_gemm2   <<<Bz*NT, 256>>>(x, Wo, bo, out);
}